// round 15
// baseline (speedup 1.0000x reference)
#include <cuda_runtime.h>

// Problem constants (fixed shapes)
#define BB   2
#define HD   4
#define HH   128
#define WW   128
#define KS   7
#define KK   49
#define NSP  9
#define SS   64
#define PLANE (HH * WW)

// TWO pixels per warp: half = lane>>4 handles pixel (h, w0+half).
// Within 16 lanes: u = (lane>>3)&1, t = lane&7 (t<7 active).
//   u=0 owns window rows 0..2 of column t, u=1 owns rows 3..6.
// Gather state is p[<=4][9] (<=36 regs) -> occupancy 5-6 CTAs/SM without
// chunking the gather burst (MLP preserved).
// Reductions: 16-lane xor butterfly (8,4,2,1). No max-subtraction.
__global__ __launch_bounds__(128)
void attn_reweight_kernel(const float* __restrict__ attn,
                          const float* __restrict__ sims,
                          const int*   __restrict__ sinds,
                          float*       __restrict__ out)
{
    const int warpid = blockIdx.x * (blockDim.x >> 5) + (threadIdx.x >> 5);
    const int lane   = threadIdx.x & 31;
    const int half   = lane >> 4;
    const int sub    = lane & 15;
    const int u      = sub >> 3;
    const int t      = sub & 7;
    const bool act   = (t < 7);
    const int  ru    = u ? 3 : 0;         // first owned row
    const int  nv    = u ? 4 : 3;         // owned row count

    const int pix0 = warpid << 1;
    const int b    = pix0 >> 14;
    const int idx  = pix0 & 16383;
    const int h    = idx >> 7;
    const int w    = (idx & 127) + half;  // idx&127 is even

    const int hs = min(max(h - KS / 2, 0), HH - KS);
    const int ws = min(max(w - KS / 2, 0), WW - KS);

    const int   wbase = hs * WW + ws + (act ? t : 6);     // lane t==7: safe addr
    const float eps0  = (sub == 7) ? 1e-10f : 0.0f;       // eps seed, one lane/pixel

    const float* sb   = sims + b * (SS * PLANE);
    const int    offc = h * WW + w;                       // center (pi)

    // sinds: lanes sub<9 load the 9 gids of this pixel, distribute via shfl
    const int sbase = (pix0 + half) * NSP;
    const int ind   = (sub < NSP) ? __ldg(&sinds[sbase + sub]) : 0;

    // ---- gather 9 planes in one burst (keep MLP) + centers ----
    float p[4][NSP], pi[NSP];
#pragma unroll
    for (int sp = 0; sp < NSP; ++sp) {
        const int gid = __shfl_sync(0xffffffffu, ind, (half << 4) + sp);
        const float* pl = sb + gid * PLANE;
#pragma unroll
        for (int i = 0; i < 4; ++i) {
            const bool valid = act && (i < nv);
            p[i][sp] = valid ? __ldg(pl + wbase + (ru + i) * WW) : 0.0f;
        }
        pi[sp] = __ldg(pl + offc);        // broadcast within half-warp
    }

    // ---- per-head compute ----
#pragma unroll
    for (int hd = 0; hd < HD; ++hd) {
        const int base = (((b * HD + hd) * HH + h) * WW + w) * KK;
        const float* ab = attn + base + t;                // k = 7*(ru+i) + t

        float a[4];
#pragma unroll
        for (int i = 0; i < 4; ++i) {
            const bool valid = act && (i < nv);
            a[i] = __expf(valid ? __ldg(ab + 7 * (ru + i)) : -1e30f);  // 0 if !valid
        }

        // d[sp] = eps + sum over owned values; 16-lane butterfly
        float d[NSP];
#pragma unroll
        for (int sp = 0; sp < NSP; ++sp) {
            float acc0 = fmaf(a[0], p[0][sp], eps0);
            float acc1 = a[1] * p[1][sp];
            acc0 = fmaf(a[2], p[2][sp], acc0);
            acc1 = fmaf(a[3], p[3][sp], acc1);
            d[sp] = acc0 + acc1;
        }
#pragma unroll
        for (int o = 8; o > 0; o >>= 1) {
#pragma unroll
            for (int sp = 0; sp < NSP; ++sp)
                d[sp] += __shfl_xor_sync(0xffffffffu, d[sp], o);
        }

        // w_sp = pi_sp / d_sp; paired reciprocals: 5 MUFU for 9 divides
        float wsp[NSP];
#pragma unroll
        for (int q = 0; q < 4; ++q) {
            const float prod = d[2 * q] * d[2 * q + 1];
            float rcp;
            asm("rcp.approx.f32 %0, %1;" : "=f"(rcp) : "f"(prod));
            wsp[2 * q]     = pi[2 * q]     * (rcp * d[2 * q + 1]);
            wsp[2 * q + 1] = pi[2 * q + 1] * (rcp * d[2 * q]);
        }
        {
            float r8;
            asm("rcp.approx.f32 %0, %1;" : "=f"(r8) : "f"(d[8]));
            wsp[8] = pi[8] * r8;
        }

        // out_k = a_k * sum_sp w_sp p_sp[k]
        float o_[4];
#pragma unroll
        for (int i = 0; i < 4; ++i) o_[i] = 0.0f;
#pragma unroll
        for (int sp = 0; sp < NSP; ++sp) {
#pragma unroll
            for (int i = 0; i < 4; ++i)
                o_[i] = fmaf(wsp[sp], p[i][sp], o_[i]);
        }

        float* ob = out + base + t;
#pragma unroll
        for (int i = 0; i < 4; ++i) {
            if (act && (i < nv))
                ob[7 * (ru + i)] = a[i] * o_[i];
        }
    }
}

extern "C" void kernel_launch(void* const* d_in, const int* in_sizes, int n_in,
                              void* d_out, int out_size)
{
    const float* attn  = (const float*)d_in[0];
    const float* sims  = (const float*)d_in[1];
    const int*   sinds = (const int*)d_in[2];
    float*       out   = (float*)d_out;

    const int warps   = BB * HH * WW / 2;        // 16384 warps (2 pixels each)
    const int threads = 128;                     // 4 warps / CTA
    const int blocks  = warps / (threads / 32);  // 4096
    attn_reweight_kernel<<<blocks, threads>>>(attn, sims, sinds, out);
}

// round 16
// speedup vs baseline: 1.2436x; 1.2436x over previous
#include <cuda_runtime.h>
#include <cstdint>

// Problem constants (fixed shapes)
#define BB   2
#define HD   4
#define HH   128
#define WW   128
#define KS   7
#define KK   49
#define NSP  9
#define SS   64
#define PLANE (HH * WW)

// Four pixels per warp: group g = lane>>3 handles pixel (h, w0+g).
// COLUMN ownership: lane t (t<7) owns window column t (k = 7r + t).
// Lane 7 carries the eps seed.
// attn (DRAM stream, the dominant uncovered stall) is prefetched for ALL 4
// heads via per-lane cp.async into smem BEFORE the gather burst; each lane
// reads back only its own values -> wait_group suffices, no barrier.
// Gather stays one monolithic LDG burst (max MLP — never chunk it).
__global__ __launch_bounds__(128)
void attn_reweight_kernel(const float* __restrict__ attn,
                          const float* __restrict__ sims,
                          const int*   __restrict__ sinds,
                          float*       __restrict__ out)
{
    // [warp][head][group][row][lane-slot] — 8 slots to keep LDS conflict-free
    __shared__ float s_attn[4][HD][4][7][8];

    const int wwarp  = threadIdx.x >> 5;
    const int lane   = threadIdx.x & 31;
    const int g      = lane >> 3;
    const int t      = lane & 7;
    const bool act   = (t < 7);

    const int warpid = blockIdx.x * 4 + wwarp;
    const int pix0 = warpid << 2;
    const int b    = pix0 >> 14;
    const int idx  = pix0 & 16383;
    const int h    = idx >> 7;
    const int w    = (idx & 127) + g;        // idx&127 multiple of 4

    const int base0      = (((b * HD) * HH + h) * WW + w) * KK;
    const int headStride = HH * WW * KK;

    // ---- issue attn prefetch first (longest latency: DRAM stream) ----
    if (act) {
#pragma unroll
        for (int hd = 0; hd < HD; ++hd) {
            const float* gp = attn + base0 + hd * headStride + t;   // k = 7r + t
#pragma unroll
            for (int r = 0; r < 7; ++r) {
                const uint32_t saddr =
                    (uint32_t)__cvta_generic_to_shared(&s_attn[wwarp][hd][g][r][t]);
                asm volatile("cp.async.ca.shared.global [%0], [%1], 4;"
                             :: "r"(saddr), "l"(gp + 7 * r) : "memory");
            }
        }
    }
    asm volatile("cp.async.commit_group;" ::: "memory");

    // ---- gather setup ----
    const int hs = min(max(h - KS / 2, 0), HH - KS);
    const int ws = min(max(w - KS / 2, 0), WW - KS);

    const int   wbase = hs * WW + ws + (act ? t : 6);   // lane 7: safe addr
    const float eps0  = act ? 0.0f : 1e-10f;            // eps seed on lane 7

    const float* sb   = sims + b * (SS * PLANE);
    const int    offc = h * WW + w;                     // center (pi)

    // sinds: coalesced per-group loads, distribute via shfl
    const int sbase = (pix0 + g) * NSP;
    const int ind_a = __ldg(&sinds[sbase + t]);
    const int ind_b = (t == 0) ? __ldg(&sinds[sbase + 8]) : 0;

    // ---- gather 9 planes in one burst (keep MLP) + centers ----
    float p[7][NSP], pi[NSP];
#pragma unroll
    for (int sp = 0; sp < NSP; ++sp) {
        const int gid = (sp < 8) ? __shfl_sync(0xffffffffu, ind_a, (g << 3) + sp)
                                 : __shfl_sync(0xffffffffu, ind_b, (g << 3));
        const float* pl = sb + gid * PLANE;
#pragma unroll
        for (int r = 0; r < 7; ++r)
            p[r][sp] = act ? __ldg(pl + wbase + r * WW) : 0.0f;
        pi[sp] = __ldg(&sb[gid * PLANE + offc]);        // broadcast within group
    }

    // attn prefetch must have landed (each lane reads its own writes)
    asm volatile("cp.async.wait_group 0;" ::: "memory");

    // ---- per-head compute ----
#pragma unroll
    for (int hd = 0; hd < HD; ++hd) {
        const int base = base0 + hd * headStride;

        float a[7];
#pragma unroll
        for (int r = 0; r < 7; ++r)
            a[r] = __expf(act ? s_attn[wwarp][hd][g][r][t] : -1e30f);  // 0 on lane 7

        // d[sp] = eps + sum_k a_k p_sp[k]; dual accumulators, 8-lane butterfly
        float d[NSP];
#pragma unroll
        for (int sp = 0; sp < NSP; ++sp) {
            float acc0 = fmaf(a[0], p[0][sp], eps0);
            float acc1 = a[1] * p[1][sp];
            acc0 = fmaf(a[2], p[2][sp], acc0);
            acc1 = fmaf(a[3], p[3][sp], acc1);
            acc0 = fmaf(a[4], p[4][sp], acc0);
            acc1 = fmaf(a[5], p[5][sp], acc1);
            acc0 = fmaf(a[6], p[6][sp], acc0);
            d[sp] = acc0 + acc1;
        }
#pragma unroll
        for (int o = 4; o > 0; o >>= 1) {
#pragma unroll
            for (int sp = 0; sp < NSP; ++sp)
                d[sp] += __shfl_xor_sync(0xffffffffu, d[sp], o);
        }

        // w_sp = pi_sp / d_sp; paired reciprocals: 5 MUFU for 9 divides
        float wsp[NSP];
#pragma unroll
        for (int q = 0; q < 4; ++q) {
            const float prod = d[2 * q] * d[2 * q + 1];
            float rcp;
            asm("rcp.approx.f32 %0, %1;" : "=f"(rcp) : "f"(prod));
            wsp[2 * q]     = pi[2 * q]     * (rcp * d[2 * q + 1]);
            wsp[2 * q + 1] = pi[2 * q + 1] * (rcp * d[2 * q]);
        }
        {
            float r8;
            asm("rcp.approx.f32 %0, %1;" : "=f"(r8) : "f"(d[8]));
            wsp[8] = pi[8] * r8;
        }

        // out_k = a_k * sum_sp w_sp p_sp[k]
        float o_[7];
#pragma unroll
        for (int r = 0; r < 7; ++r) o_[r] = 0.0f;
#pragma unroll
        for (int sp = 0; sp < NSP; ++sp) {
#pragma unroll
            for (int r = 0; r < 7; ++r)
                o_[r] = fmaf(wsp[sp], p[r][sp], o_[r]);
        }

        float* ob = out + base + t;
        if (act) {
#pragma unroll
            for (int r = 0; r < 7; ++r)
                ob[7 * r] = a[r] * o_[r];
        }
    }
}

extern "C" void kernel_launch(void* const* d_in, const int* in_sizes, int n_in,
                              void* d_out, int out_size)
{
    const float* attn  = (const float*)d_in[0];
    const float* sims  = (const float*)d_in[1];
    const int*   sinds = (const int*)d_in[2];
    float*       out   = (float*)d_out;

    const int warps   = BB * HH * WW / 4;        // 8192 warps (4 pixels each)
    const int threads = 128;                     // 4 warps / CTA
    const int blocks  = warps / (threads / 32);  // 2048
    attn_reweight_kernel<<<blocks, threads>>>(attn, sims, sinds, out);
}